// round 14
// baseline (speedup 1.0000x reference)
#include <cuda_runtime.h>
#include <cuda_fp16.h>
#include <math.h>
#include <stdint.h>

#define B_  128
#define LQ_ 32
#define LD_ 512
#define H_  768
#define C_  128
#define NSPL 8           // score split-K chunks (512/64)
#define KROWS 64         // k-rows per score CTA
#define KPAD 776         // B smem row stride (halfs); 776*2=1552=16*97
#define QBLK (B_ * LQ_ / 256)    // 16 query gemm blocks
#define DBLK (B_ * LD_ / 256)    // 256 doc gemm blocks

// Scratch (__device__ globals: allocation-free rule)
__device__ __half g_dvecs[B_ * LD_ * C_];   // 16.7 MB
__device__ __half g_qvecs[B_ * LQ_ * C_];   // 1 MB
__device__ __half g_Wth[C_ * H_];           // W_comp transposed, fp16
__device__ float  g_pmax[B_ * NSPL * LQ_];  // split-K partial maxima
__device__ float  g_cls[B_];                // CLS dot per batch
__device__ int    g_cnt[B_];                // zero-init; self-resetting

__device__ __forceinline__ uint32_t smem_u32(const void* p) {
    uint32_t a;
    asm("{ .reg .u64 t; cvta.to.shared.u64 t, %1; cvt.u32.u64 %0, t; }"
        : "=r"(a) : "l"(p));
    return a;
}
__device__ __forceinline__ void cp16(void* dst, const void* src) {
    asm volatile("cp.async.cg.shared.global [%0], [%1], 16;"
                 :: "r"(smem_u32(dst)), "l"(src));
}
#define CP_COMMIT() asm volatile("cp.async.commit_group;" ::: "memory")
#define CP_WAIT0()  asm volatile("cp.async.wait_group 0;" ::: "memory")

__device__ __forceinline__ uint32_t h2u(float x, float y) {
    __half2 h = __floats2half2_rn(x, y);
    return *(uint32_t*)&h;
}
__device__ __forceinline__ uint32_t h2u2(float2 v) { return h2u(v.x, v.y); }

__device__ __forceinline__ void mma_f16(float c[4], uint32_t a0, uint32_t a1,
                                        uint32_t a2, uint32_t a3,
                                        uint32_t b0, uint32_t b1) {
    asm volatile(
        "mma.sync.aligned.m16n8k16.row.col.f32.f16.f16.f32 "
        "{%0,%1,%2,%3}, {%4,%5,%6,%7}, {%8,%9}, {%0,%1,%2,%3};"
        : "+f"(c[0]), "+f"(c[1]), "+f"(c[2]), "+f"(c[3])
        : "r"(a0), "r"(a1), "r"(a2), "r"(a3), "r"(b0), "r"(b1));
}

// ---------------------------------------------------------------------------
// Prep: blocks 0..95 tile-transpose W_comp [H,C] -> g_Wth [C,H] fp16
//       (32x32 fp32 smem tiles, coalesced read AND write);
//       blocks 96..223 compute CLS dots -> g_cls[b]
// ---------------------------------------------------------------------------
__global__ void prep_all(const float* __restrict__ W,
                         const float* __restrict__ qh,
                         const float* __restrict__ dhid)
{
    if (blockIdx.x < 96) {
        __shared__ float tile[32][33];
        const int r0 = (blockIdx.x >> 2) * 32;   // k-dim tile (768/32=24)
        const int c0 = (blockIdx.x & 3) * 32;    // c-dim tile (128/32=4)
        const int t  = threadIdx.x;
        const int rr = t >> 5, cc = t & 31;
#pragma unroll
        for (int u = 0; u < 4; u++) {
            int r = rr + 8 * u;
            tile[cc][r] = W[(size_t)(r0 + r) * C_ + c0 + cc];
        }
        __syncthreads();
#pragma unroll
        for (int u = 0; u < 4; u++) {
            int c = rr + 8 * u;
            g_Wth[(size_t)(c0 + c) * H_ + r0 + cc] = __float2half_rn(tile[c][cc]);
        }
    } else {
        __shared__ float s_red[256];
        const int b = blockIdx.x - 96;
        const int t = threadIdx.x;
        const float* qp = qh   + (size_t)b * LQ_ * H_;
        const float* dp = dhid + (size_t)b * LD_ * H_;
        float p = 0.f;
        for (int h = t; h < H_; h += 256) p += qp[h] * dp[h];
        s_red[t] = p;
        __syncthreads();
        for (int s = 128; s > 0; s >>= 1) {
            if (t < s) s_red[t] += s_red[t + s];
            __syncthreads();
        }
        if (t == 0) g_cls[b] = s_red[0];
    }
}

// ---------------------------------------------------------------------------
// B-resident projection GEMM: full W (128x768 fp16 = 194KB) in smem,
// A fragments streamed straight from global (each row owned by ONE warp ->
// every A element read once from DRAM). 512 threads = 16 warps x m16xn128.
// CTA tile 256 rows x 128 cols; query blocks 0..15, doc blocks 16..271.
// Doc: warp-local importance gating + dm mask -> g_dvecs; query: qm.
// ---------------------------------------------------------------------------
#define GEMM_SMEM (C_ * KPAD * 2)   // 198656 B

__global__ void __launch_bounds__(512) gemm_all(
    const float* __restrict__ Xq,
    const float* __restrict__ Xd,
    const float* __restrict__ bcomp,
    const float* __restrict__ wstop,
    const float* __restrict__ bstop,
    const int*   __restrict__ qmask,
    const int*   __restrict__ dmask)
{
    extern __shared__ __half Bs[];   // [128][KPAD]

    const bool isq = blockIdx.x < QBLK;
    const int  blk = isq ? blockIdx.x : blockIdx.x - QBLK;
    const float* X    = isq ? Xq : Xd;
    const int*   mask = isq ? qmask : dmask;

    const int t    = threadIdx.x;
    const int lane = t & 31;
    const int w    = t >> 5;
    const int g    = lane >> 2, tig = lane & 3;
    const int row0 = blk * 256;

    // ---- load whole B into smem: 128 cols x 768 halfs = 12288 cp16 ----
#pragma unroll
    for (int u = 0; u < 24; u++) {
        int i   = t + u * 512;
        int col = i / 96;
        int k8  = (i % 96) * 8;
        cp16(&Bs[col * KPAD + k8], g_Wth + (size_t)col * H_ + k8);
    }
    CP_COMMIT();

    const int r0 = row0 + w * 16 + g;       // this thread's first row
    const float* A0 = X + (size_t)r0 * H_ + 2 * tig;
    const float* A1 = A0 + (size_t)8 * H_;

    float acc[16][4];
#pragma unroll
    for (int nt = 0; nt < 16; nt++)
#pragma unroll
        for (int x = 0; x < 4; x++) acc[nt][x] = 0.f;

    // prefetch k-block 0 (k-steps 0 and 16)
    float2 cur[8];
    cur[0] = *(const float2*)(A0 + 0);
    cur[1] = *(const float2*)(A1 + 0);
    cur[2] = *(const float2*)(A0 + 8);
    cur[3] = *(const float2*)(A1 + 8);
    cur[4] = *(const float2*)(A0 + 16);
    cur[5] = *(const float2*)(A1 + 16);
    cur[6] = *(const float2*)(A0 + 24);
    cur[7] = *(const float2*)(A1 + 24);

    CP_WAIT0();
    __syncthreads();

    for (int kt = 0; kt < H_; kt += 32) {
        float2 nxt[8];
        if (kt + 32 < H_) {
            nxt[0] = *(const float2*)(A0 + kt + 32);
            nxt[1] = *(const float2*)(A1 + kt + 32);
            nxt[2] = *(const float2*)(A0 + kt + 40);
            nxt[3] = *(const float2*)(A1 + kt + 40);
            nxt[4] = *(const float2*)(A0 + kt + 48);
            nxt[5] = *(const float2*)(A1 + kt + 48);
            nxt[6] = *(const float2*)(A0 + kt + 56);
            nxt[7] = *(const float2*)(A1 + kt + 56);
        }
#pragma unroll
        for (int hf = 0; hf < 2; hf++) {
            const int k0 = kt + hf * 16;
            uint32_t a0 = h2u2(cur[hf * 4 + 0]);
            uint32_t a1 = h2u2(cur[hf * 4 + 1]);
            uint32_t a2 = h2u2(cur[hf * 4 + 2]);
            uint32_t a3 = h2u2(cur[hf * 4 + 3]);
#pragma unroll
            for (int nt = 0; nt < 16; nt++) {
                const __half* bp = &Bs[(nt * 8 + g) * KPAD + k0 + 2 * tig];
                uint32_t b0 = *(const uint32_t*)bp;
                uint32_t b1 = *(const uint32_t*)(bp + 8);
                mma_f16(acc[nt], a0, a1, a2, a3, b0, b1);
            }
        }
#pragma unroll
        for (int j = 0; j < 8; j++) cur[j] = nxt[j];
    }

    // ---- warp-local epilogue (rows exclusive to this warp) ----
    float bb0[16], bb1[16];
#pragma unroll
    for (int nt = 0; nt < 16; nt++) {
        int c0 = nt * 8 + 2 * tig;
        bb0[nt] = bcomp[c0];
        bb1[nt] = bcomp[c0 + 1];
    }

    const float m0 = (float)mask[r0];
    const float m1 = (float)mask[r0 + 8];
    float scale0, scale1;
    if (!isq) {
        float p0 = 0.f, p1 = 0.f;
#pragma unroll
        for (int nt = 0; nt < 16; nt++) {
            int c0 = nt * 8 + 2 * tig;
            float w0 = wstop[c0], w1 = wstop[c0 + 1];
            p0 += (acc[nt][0] + bb0[nt]) * w0 + (acc[nt][1] + bb1[nt]) * w1;
            p1 += (acc[nt][2] + bb0[nt]) * w0 + (acc[nt][3] + bb1[nt]) * w1;
        }
        p0 += __shfl_xor_sync(0xffffffffu, p0, 1);
        p0 += __shfl_xor_sync(0xffffffffu, p0, 2);
        p1 += __shfl_xor_sync(0xffffffffu, p1, 1);
        p1 += __shfl_xor_sync(0xffffffffu, p1, 2);
        float bst = bstop[0];
        scale0 = fmaxf(p0 + bst, 0.f) * m0;
        scale1 = fmaxf(p1 + bst, 0.f) * m1;
    } else {
        scale0 = m0;
        scale1 = m1;
    }

    __half* OUT = isq ? g_qvecs : g_dvecs;
#pragma unroll
    for (int nt = 0; nt < 16; nt++) {
        int c0 = nt * 8 + 2 * tig;
        uint32_t v0 = h2u((acc[nt][0] + bb0[nt]) * scale0,
                          (acc[nt][1] + bb1[nt]) * scale0);
        uint32_t v1 = h2u((acc[nt][2] + bb0[nt]) * scale1,
                          (acc[nt][3] + bb1[nt]) * scale1);
        *(uint32_t*)(OUT + (size_t)r0 * C_ + c0)       = v0;
        *(uint32_t*)(OUT + (size_t)(r0 + 8) * C_ + c0) = v1;
    }
}

// ---------------------------------------------------------------------------
// Fused split-K scoring: CTA (b, ci) computes masked max over 64 k-rows
// -> g_pmax; the LAST CTA per batch (atomic counter) merges, adds CLS,
// applies sigmoid merge, writes output, and resets the counter.
// ---------------------------------------------------------------------------
#define QPh 136
#define SP_SMEM ((32 * QPh + KROWS * QPh) * 2 + 128 * 4 + KROWS * 4)

__global__ void __launch_bounds__(256) score_fused(
    const int* __restrict__ dmask,
    const int* __restrict__ qmask,
    const float* __restrict__ merger,
    float* __restrict__ out)
{
    extern __shared__ char smc[];
    __half* qs   = (__half*)smc;                        // 32 * QPh
    __half* ds   = qs + 32 * QPh;                       // KROWS * QPh
    float*  redm = (float*)(ds + KROWS * QPh);          // 128 floats
    int*    dmch = (int*)(redm + 128);                  // KROWS ints
    __shared__ int s_last;

    const int b    = blockIdx.x >> 3;
    const int ci   = blockIdx.x & 7;
    const int k0g  = ci * KROWS;
    const int t    = threadIdx.x;
    const int lane = t & 31;
    const int w    = t >> 5;
    const int g    = lane >> 2, tig = lane & 3;
    const int wq   = w & 1;    // q half (16 rows)
    const int wk   = w >> 1;   // k group (16 rows)

    // Stage q_vecs [32 x 128] fp16
#pragma unroll
    for (int u = 0; u < 2; u++) {
        int i  = t + u * 256;
        int q  = i >> 4;
        int c8 = (i & 15) * 8;
        *(uint4*)&qs[q * QPh + c8] = *(const uint4*)(
            g_qvecs + (size_t)b * LQ_ * C_ + (size_t)q * C_ + c8);
    }
    // Stage d chunk [64 x 128] fp16
#pragma unroll
    for (int u = 0; u < 4; u++) {
        int i  = t + u * 256;
        int k  = i >> 4;
        int c8 = (i & 15) * 8;
        *(uint4*)&ds[k * QPh + c8] = *(const uint4*)(
            g_dvecs + (size_t)b * LD_ * C_ + (size_t)(k0g + k) * C_ + c8);
    }
    if (t < KROWS) dmch[t] = dmask[b * LD_ + k0g + t];
    __syncthreads();

    float acc[2][4];
#pragma unroll
    for (int nt = 0; nt < 2; nt++)
#pragma unroll
        for (int x = 0; x < 4; x++) acc[nt][x] = 0.f;

#pragma unroll
    for (int cs = 0; cs < 8; cs++) {
        const int c0 = cs * 16;
        uint32_t a0 = *(const uint32_t*)&qs[(wq * 16 + g) * QPh + c0 + 2 * tig];
        uint32_t a1 = *(const uint32_t*)&qs[(wq * 16 + g + 8) * QPh + c0 + 2 * tig];
        uint32_t a2 = *(const uint32_t*)&qs[(wq * 16 + g) * QPh + c0 + 8 + 2 * tig];
        uint32_t a3 = *(const uint32_t*)&qs[(wq * 16 + g + 8) * QPh + c0 + 8 + 2 * tig];
#pragma unroll
        for (int nt = 0; nt < 2; nt++) {
            int n = wk * 16 + nt * 8 + g;
            uint32_t b0 = *(const uint32_t*)&ds[n * QPh + c0 + 2 * tig];
            uint32_t b1 = *(const uint32_t*)&ds[n * QPh + c0 + 8 + 2 * tig];
            mma_f16(acc[nt], a0, a1, a2, a3, b0, b1);
        }
    }

    float mx0 = -1000.f, mx1 = -1000.f;
#pragma unroll
    for (int nt = 0; nt < 2; nt++) {
        int n0 = wk * 16 + nt * 8 + 2 * tig;
        if (dmch[n0]) {
            mx0 = fmaxf(mx0, acc[nt][0]);
            mx1 = fmaxf(mx1, acc[nt][2]);
        }
        if (dmch[n0 + 1]) {
            mx0 = fmaxf(mx0, acc[nt][1]);
            mx1 = fmaxf(mx1, acc[nt][3]);
        }
    }
    mx0 = fmaxf(mx0, __shfl_xor_sync(0xffffffffu, mx0, 1));
    mx0 = fmaxf(mx0, __shfl_xor_sync(0xffffffffu, mx0, 2));
    mx1 = fmaxf(mx1, __shfl_xor_sync(0xffffffffu, mx1, 1));
    mx1 = fmaxf(mx1, __shfl_xor_sync(0xffffffffu, mx1, 2));
    __syncthreads();
    if (tig == 0) {
        redm[(wq * 16 + g) * 4 + wk]     = mx0;
        redm[(wq * 16 + g + 8) * 4 + wk] = mx1;
    }
    __syncthreads();

    if (t < 32) {
        float m = fmaxf(fmaxf(redm[t * 4 + 0], redm[t * 4 + 1]),
                        fmaxf(redm[t * 4 + 2], redm[t * 4 + 3]));
        g_pmax[(b * NSPL + ci) * LQ_ + t] = m;
    }

    // ---- last-CTA merge ----
    __threadfence();
    if (t == 0) {
        int old = atomicAdd(&g_cnt[b], 1);
        s_last = (old == NSPL - 1);
    }
    __syncthreads();
    if (!s_last) return;
    __threadfence();   // acquire: see other CTAs' g_pmax writes

    if (t < 32) {
        float m = -1000.f;
#pragma unroll
        for (int ci2 = 0; ci2 < NSPL; ci2++)
            m = fmaxf(m, g_pmax[(b * NSPL + ci2) * LQ_ + t]);
        float term = qmask[b * LQ_ + t] ? m : 0.f;
#pragma unroll
        for (int o = 16; o >= 1; o >>= 1)
            term += __shfl_xor_sync(0xffffffffu, term, o);
        if (t == 0) {
            float w_  = 1.f / (1.f + expf(-merger[0]));
            float cls = g_cls[b] * w_;
            float ts  = term * (1.f - w_);
            out[b]          = cls + ts;
            out[B_ + b]     = cls;
            out[2 * B_ + b] = ts;
            g_cnt[b] = 0;   // reset for next graph replay
        }
    }
}

extern "C" void kernel_launch(void* const* d_in, const int* in_sizes, int n_in,
                              void* d_out, int out_size)
{
    const float* query_hidden = (const float*)d_in[0];
    const float* doc_hidden   = (const float*)d_in[1];
    const int*   query_mask   = (const int*)  d_in[2];
    const int*   doc_mask     = (const int*)  d_in[3];
    const float* W_comp       = (const float*)d_in[4];
    const float* b_comp       = (const float*)d_in[5];
    const float* w_stop       = (const float*)d_in[6];
    const float* b_stop       = (const float*)d_in[7];
    const float* score_merger = (const float*)d_in[8];
    float* out = (float*)d_out;

    cudaFuncSetAttribute(gemm_all,
                         cudaFuncAttributeMaxDynamicSharedMemorySize, GEMM_SMEM);
    cudaFuncSetAttribute(score_fused,
                         cudaFuncAttributeMaxDynamicSharedMemorySize, SP_SMEM);

    prep_all<<<224, 256>>>(W_comp, query_hidden, doc_hidden);
    gemm_all<<<QBLK + DBLK, 512, GEMM_SMEM>>>(
        query_hidden, doc_hidden, b_comp, w_stop, b_stop,
        query_mask, doc_mask);
    score_fused<<<B_ * NSPL, 256, SP_SMEM>>>(
        doc_mask, query_mask, score_merger, out);
}

// round 15
// speedup vs baseline: 1.0818x; 1.0818x over previous
#include <cuda_runtime.h>
#include <cuda_fp16.h>
#include <math.h>
#include <stdint.h>

#define B_  128
#define LQ_ 32
#define LD_ 512
#define H_  768
#define C_  128
#define KCH 32
#define NCH (H_ / KCH)   // 24 K-chunks
#define AP  36           // A [row][k] pad (fp32)
#define BPh 40           // B [col][k] pad (fp16)
#define STG 4            // cp.async pipeline stages (3 chunks in flight)
#define NSPL 8           // score split-K chunks (512/64)
#define KROWS 64         // k-rows per score CTA
#define QBLK (B_ * LQ_ / 128)    // 32 query gemm blocks
#define DBLK (B_ * LD_ / 128)    // 512 doc gemm blocks

// Scratch (__device__ globals: allocation-free rule)
__device__ __half g_dvecs[B_ * LD_ * C_];   // 16.7 MB
__device__ __half g_qvecs[B_ * LQ_ * C_];   // 1 MB
__device__ __half g_Wth[C_ * H_];           // W_comp transposed, fp16
__device__ float  g_pmax[B_ * NSPL * LQ_];  // split-K partial maxima
__device__ float  g_cls[B_];                // CLS dot per batch
__device__ int    g_cnt[B_];                // zero-init; self-resetting

__device__ __forceinline__ uint32_t smem_u32(const void* p) {
    uint32_t a;
    asm("{ .reg .u64 t; cvta.to.shared.u64 t, %1; cvt.u32.u64 %0, t; }"
        : "=r"(a) : "l"(p));
    return a;
}
__device__ __forceinline__ void cp16(void* dst, const void* src) {
    asm volatile("cp.async.cg.shared.global [%0], [%1], 16;"
                 :: "r"(smem_u32(dst)), "l"(src));
}
#define CP_COMMIT() asm volatile("cp.async.commit_group;" ::: "memory")
#define CP_WAIT2()  asm volatile("cp.async.wait_group 2;" ::: "memory")

__device__ __forceinline__ uint32_t h2u(float x, float y) {
    __half2 h = __floats2half2_rn(x, y);
    return *(uint32_t*)&h;
}

__device__ __forceinline__ void mma_f16(float c[4], uint32_t a0, uint32_t a1,
                                        uint32_t a2, uint32_t a3,
                                        uint32_t b0, uint32_t b1) {
    asm volatile(
        "mma.sync.aligned.m16n8k16.row.col.f32.f16.f16.f32 "
        "{%0,%1,%2,%3}, {%4,%5,%6,%7}, {%8,%9}, {%0,%1,%2,%3};"
        : "+f"(c[0]), "+f"(c[1]), "+f"(c[2]), "+f"(c[3])
        : "r"(a0), "r"(a1), "r"(a2), "r"(a3), "r"(b0), "r"(b1));
}

// ---------------------------------------------------------------------------
// Prep: blocks 0..95 tile-transpose W_comp [H,C] -> g_Wth [C,H] fp16
//       (32x32 fp32 smem tiles, coalesced read AND write);
//       blocks 96..223 compute CLS dots -> g_cls[b]
// ---------------------------------------------------------------------------
__global__ void prep_all(const float* __restrict__ W,
                         const float* __restrict__ qh,
                         const float* __restrict__ dhid)
{
    if (blockIdx.x < 96) {
        __shared__ float tile[32][33];
        const int r0 = (blockIdx.x >> 2) * 32;   // k-dim tile (768/32=24)
        const int c0 = (blockIdx.x & 3) * 32;    // c-dim tile (128/32=4)
        const int t  = threadIdx.x;
        const int rr = t >> 5, cc = t & 31;
#pragma unroll
        for (int u = 0; u < 4; u++) {
            int r = rr + 8 * u;
            tile[cc][r] = W[(size_t)(r0 + r) * C_ + c0 + cc];
        }
        __syncthreads();
#pragma unroll
        for (int u = 0; u < 4; u++) {
            int c = rr + 8 * u;
            g_Wth[(size_t)(c0 + c) * H_ + r0 + cc] = __float2half_rn(tile[c][cc]);
        }
    } else {
        __shared__ float s_red[256];
        const int b = blockIdx.x - 96;
        const int t = threadIdx.x;
        const float* qp = qh   + (size_t)b * LQ_ * H_;
        const float* dp = dhid + (size_t)b * LD_ * H_;
        float p = 0.f;
        for (int h = t; h < H_; h += 256) p += qp[h] * dp[h];
        s_red[t] = p;
        __syncthreads();
        for (int s = 128; s > 0; s >>= 1) {
            if (t < s) s_red[t] += s_red[t + s];
            __syncthreads();
        }
        if (t == 0) g_cls[b] = s_red[0];
    }
}

// ---------------------------------------------------------------------------
// Merged projection GEMM (query blocks 0..31, doc blocks 32..543).
// 128x128 tile/CTA, 8 warps = 4m x 2n (warp m32 x n64).
// 4-stage cp.async pipeline (3 chunks in flight), mma.sync fp16, fp32 accum.
// Doc: fused importance gating + dm mask -> g_dvecs; query: qm -> g_qvecs.
// ---------------------------------------------------------------------------
#define A_BYTES (128 * AP * 4)
#define B_BYTES (128 * BPh * 2)
#define STAGE_BYTES (A_BYTES + B_BYTES)
#define GEMM_SMEM (STG * STAGE_BYTES)   // 114688 B; x2 CTAs = 229376 <= 233472

__global__ void __launch_bounds__(256, 2) gemm_all(
    const float* __restrict__ Xq,
    const float* __restrict__ Xd,
    const float* __restrict__ bcomp,
    const float* __restrict__ wstop,
    const float* __restrict__ bstop,
    const int*   __restrict__ qmask,
    const int*   __restrict__ dmask)
{
    extern __shared__ char smg[];

    const bool isq = blockIdx.x < QBLK;
    const int  blk = isq ? blockIdx.x : blockIdx.x - QBLK;
    const float* X    = isq ? Xq : Xd;
    const int*   mask = isq ? qmask : dmask;

    const int t    = threadIdx.x;
    const int lane = t & 31;
    const int w    = t >> 5;
    const int wm   = w >> 1, wn = w & 1;
    const int g    = lane >> 2, tig = lane & 3;
    const int Rl   = wm * 32, Cl = wn * 64;
    const int row0 = blk * 128;

    // A staging: row = t>>3 (+32u), col quad = (t&7)*4 floats
    const int sar = t >> 3;
    const int sak = (t & 7) * 4;
    const float* Xp = X + (size_t)(row0 + sar) * H_ + sak;

    float acc[2][8][4];
#pragma unroll
    for (int mt = 0; mt < 2; mt++)
#pragma unroll
        for (int nt = 0; nt < 8; nt++)
#pragma unroll
            for (int x = 0; x < 4; x++) acc[mt][nt][x] = 0.f;

    // ---- prologue: stage chunks 0,1,2 ----
#pragma unroll
    for (int s = 0; s < 3; s++) {
        float*  As = (float*)(smg + s * STAGE_BYTES);
        __half* Bs = (__half*)(smg + s * STAGE_BYTES + A_BYTES);
        const int kt = s * KCH;
#pragma unroll
        for (int u = 0; u < 4; u++)
            cp16(&As[(sar + 32 * u) * AP + sak], Xp + (size_t)(32 * u) * H_ + kt);
#pragma unroll
        for (int u = 0; u < 2; u++) {
            int i  = t + u * 256;
            int cb = i >> 2;
            int k8 = (i & 3) * 8;
            cp16(&Bs[cb * BPh + k8], g_Wth + (size_t)cb * H_ + kt + k8);
        }
        CP_COMMIT();
    }

    int snext = 3;
    for (int ch = 0; ch < NCH; ch++) {
        CP_WAIT2();          // chunk ch resident (<=2 newer groups pending)
        __syncthreads();

        if (ch + 3 < NCH) {
            float*  As = (float*)(smg + snext * STAGE_BYTES);
            __half* Bs = (__half*)(smg + snext * STAGE_BYTES + A_BYTES);
            const int kt = (ch + 3) * KCH;
#pragma unroll
            for (int u = 0; u < 4; u++)
                cp16(&As[(sar + 32 * u) * AP + sak],
                     Xp + (size_t)(32 * u) * H_ + kt);
#pragma unroll
            for (int u = 0; u < 2; u++) {
                int i  = t + u * 256;
                int cb = i >> 2;
                int k8 = (i & 3) * 8;
                cp16(&Bs[cb * BPh + k8], g_Wth + (size_t)cb * H_ + kt + k8);
            }
            CP_COMMIT();
            snext = (snext + 1 == STG) ? 0 : snext + 1;
        } else {
            CP_COMMIT();     // empty group keeps wait_group cadence
        }

        const int sc = ch % STG;
        const float*  As = (const float*)(smg + sc * STAGE_BYTES);
        const __half* Bs = (const __half*)(smg + sc * STAGE_BYTES + A_BYTES);

#pragma unroll
        for (int ks = 0; ks < 2; ks++) {
            const int k0 = ks * 16;
            uint32_t a[2][4];
#pragma unroll
            for (int mt = 0; mt < 2; mt++) {
                int r = Rl + mt * 16 + g;
                float2 f0 = *(const float2*)&As[r * AP + k0 + 2 * tig];
                float2 f1 = *(const float2*)&As[(r + 8) * AP + k0 + 2 * tig];
                float2 f2 = *(const float2*)&As[r * AP + k0 + 8 + 2 * tig];
                float2 f3 = *(const float2*)&As[(r + 8) * AP + k0 + 8 + 2 * tig];
                a[mt][0] = h2u(f0.x, f0.y);
                a[mt][1] = h2u(f1.x, f1.y);
                a[mt][2] = h2u(f2.x, f2.y);
                a[mt][3] = h2u(f3.x, f3.y);
            }
#pragma unroll
            for (int nt = 0; nt < 8; nt++) {
                int c = Cl + nt * 8 + g;
                uint32_t b0 = *(const uint32_t*)&Bs[c * BPh + k0 + 2 * tig];
                uint32_t b1 = *(const uint32_t*)&Bs[c * BPh + k0 + 8 + 2 * tig];
                mma_f16(acc[0][nt], a[0][0], a[0][1], a[0][2], a[0][3], b0, b1);
                mma_f16(acc[1][nt], a[1][0], a[1][1], a[1][2], a[1][3], b0, b1);
            }
        }
    }
    __syncthreads();

    // ---- Epilogue ----
    float bb[8][2];
#pragma unroll
    for (int nt = 0; nt < 8; nt++) {
        int c0 = Cl + nt * 8 + 2 * tig;
        bb[nt][0] = bcomp[c0];
        bb[nt][1] = bcomp[c0 + 1];
    }

    float (*spart)[2] = (float(*)[2])smg;        // 128 x 2 partials
    float* sscale     = (float*)smg + 256;       // 128 scales

    if (!isq) {
        float ws[8][2];
#pragma unroll
        for (int nt = 0; nt < 8; nt++) {
            int c0 = Cl + nt * 8 + 2 * tig;
            ws[nt][0] = wstop[c0];
            ws[nt][1] = wstop[c0 + 1];
        }
        float p[2][2] = {{0.f, 0.f}, {0.f, 0.f}};
#pragma unroll
        for (int mt = 0; mt < 2; mt++)
#pragma unroll
            for (int nt = 0; nt < 8; nt++) {
                p[mt][0] += (acc[mt][nt][0] + bb[nt][0]) * ws[nt][0]
                          + (acc[mt][nt][1] + bb[nt][1]) * ws[nt][1];
                p[mt][1] += (acc[mt][nt][2] + bb[nt][0]) * ws[nt][0]
                          + (acc[mt][nt][3] + bb[nt][1]) * ws[nt][1];
            }
#pragma unroll
        for (int mt = 0; mt < 2; mt++)
#pragma unroll
            for (int h = 0; h < 2; h++) {
                float v = p[mt][h];
                v += __shfl_xor_sync(0xffffffffu, v, 1);
                v += __shfl_xor_sync(0xffffffffu, v, 2);
                p[mt][h] = v;
            }
        if (tig == 0) {
#pragma unroll
            for (int mt = 0; mt < 2; mt++)
#pragma unroll
                for (int h = 0; h < 2; h++)
                    spart[Rl + mt * 16 + g + 8 * h][wn] = p[mt][h];
        }
        __syncthreads();
        if (t < 128) {
            float pp = spart[t][0] + spart[t][1] + bstop[0];
            sscale[t] = fmaxf(pp, 0.f) * (float)mask[row0 + t];
        }
        __syncthreads();
    } else {
        if (t < 128) sscale[t] = (float)mask[row0 + t];
        __syncthreads();
    }

    __half* OUT = isq ? g_qvecs : g_dvecs;
#pragma unroll
    for (int mt = 0; mt < 2; mt++)
#pragma unroll
        for (int h = 0; h < 2; h++) {
            int lrow = Rl + mt * 16 + g + 8 * h;
            float s  = sscale[lrow];
            int row  = row0 + lrow;
#pragma unroll
            for (int nt = 0; nt < 8; nt++) {
                int c0 = Cl + nt * 8 + 2 * tig;
                uint32_t hv = h2u((acc[mt][nt][2 * h + 0] + bb[nt][0]) * s,
                                  (acc[mt][nt][2 * h + 1] + bb[nt][1]) * s);
                *(uint32_t*)(OUT + (size_t)row * C_ + c0) = hv;
            }
        }
}

// ---------------------------------------------------------------------------
// Fused split-K scoring: CTA (b, ci) computes masked max over 64 k-rows
// -> g_pmax; the LAST CTA per batch (atomic counter) merges, adds CLS,
// applies sigmoid merge, writes output, and resets the counter.
// ---------------------------------------------------------------------------
#define QPh 136
#define SP_SMEM ((32 * QPh + KROWS * QPh) * 2 + 128 * 4 + KROWS * 4)

__global__ void __launch_bounds__(256) score_fused(
    const int* __restrict__ dmask,
    const int* __restrict__ qmask,
    const float* __restrict__ merger,
    float* __restrict__ out)
{
    extern __shared__ char smc[];
    __half* qs   = (__half*)smc;                        // 32 * QPh
    __half* ds   = qs + 32 * QPh;                       // KROWS * QPh
    float*  redm = (float*)(ds + KROWS * QPh);          // 128 floats
    int*    dmch = (int*)(redm + 128);                  // KROWS ints
    __shared__ int s_last;

    const int b    = blockIdx.x >> 3;
    const int ci   = blockIdx.x & 7;
    const int k0g  = ci * KROWS;
    const int t    = threadIdx.x;
    const int lane = t & 31;
    const int w    = t >> 5;
    const int g    = lane >> 2, tig = lane & 3;
    const int wq   = w & 1;    // q half (16 rows)
    const int wk   = w >> 1;   // k group (16 rows)

    // Stage q_vecs [32 x 128] fp16
#pragma unroll
    for (int u = 0; u < 2; u++) {
        int i  = t + u * 256;
        int q  = i >> 4;
        int c8 = (i & 15) * 8;
        *(uint4*)&qs[q * QPh + c8] = *(const uint4*)(
            g_qvecs + (size_t)b * LQ_ * C_ + (size_t)q * C_ + c8);
    }
    // Stage d chunk [64 x 128] fp16
#pragma unroll
    for (int u = 0; u < 4; u++) {
        int i  = t + u * 256;
        int k  = i >> 4;
        int c8 = (i & 15) * 8;
        *(uint4*)&ds[k * QPh + c8] = *(const uint4*)(
            g_dvecs + (size_t)b * LD_ * C_ + (size_t)(k0g + k) * C_ + c8);
    }
    if (t < KROWS) dmch[t] = dmask[b * LD_ + k0g + t];
    __syncthreads();

    float acc[2][4];
#pragma unroll
    for (int nt = 0; nt < 2; nt++)
#pragma unroll
        for (int x = 0; x < 4; x++) acc[nt][x] = 0.f;

#pragma unroll
    for (int cs = 0; cs < 8; cs++) {
        const int c0 = cs * 16;
        uint32_t a0 = *(const uint32_t*)&qs[(wq * 16 + g) * QPh + c0 + 2 * tig];
        uint32_t a1 = *(const uint32_t*)&qs[(wq * 16 + g + 8) * QPh + c0 + 2 * tig];
        uint32_t a2 = *(const uint32_t*)&qs[(wq * 16 + g) * QPh + c0 + 8 + 2 * tig];
        uint32_t a3 = *(const uint32_t*)&qs[(wq * 16 + g + 8) * QPh + c0 + 8 + 2 * tig];
#pragma unroll
        for (int nt = 0; nt < 2; nt++) {
            int n = wk * 16 + nt * 8 + g;
            uint32_t b0 = *(const uint32_t*)&ds[n * QPh + c0 + 2 * tig];
            uint32_t b1 = *(const uint32_t*)&ds[n * QPh + c0 + 8 + 2 * tig];
            mma_f16(acc[nt], a0, a1, a2, a3, b0, b1);
        }
    }

    float mx0 = -1000.f, mx1 = -1000.f;
#pragma unroll
    for (int nt = 0; nt < 2; nt++) {
        int n0 = wk * 16 + nt * 8 + 2 * tig;
        if (dmch[n0]) {
            mx0 = fmaxf(mx0, acc[nt][0]);
            mx1 = fmaxf(mx1, acc[nt][2]);
        }
        if (dmch[n0 + 1]) {
            mx0 = fmaxf(mx0, acc[nt][1]);
            mx1 = fmaxf(mx1, acc[nt][3]);
        }
    }
    mx0 = fmaxf(mx0, __shfl_xor_sync(0xffffffffu, mx0, 1));
    mx0 = fmaxf(mx0, __shfl_xor_sync(0xffffffffu, mx0, 2));
    mx1 = fmaxf(mx1, __shfl_xor_sync(0xffffffffu, mx1, 1));
    mx1 = fmaxf(mx1, __shfl_xor_sync(0xffffffffu, mx1, 2));
    __syncthreads();
    if (tig == 0) {
        redm[(wq * 16 + g) * 4 + wk]     = mx0;
        redm[(wq * 16 + g + 8) * 4 + wk] = mx1;
    }
    __syncthreads();

    if (t < 32) {
        float m = fmaxf(fmaxf(redm[t * 4 + 0], redm[t * 4 + 1]),
                        fmaxf(redm[t * 4 + 2], redm[t * 4 + 3]));
        g_pmax[(b * NSPL + ci) * LQ_ + t] = m;
    }

    // ---- last-CTA merge ----
    __threadfence();
    if (t == 0) {
        int old = atomicAdd(&g_cnt[b], 1);
        s_last = (old == NSPL - 1);
    }
    __syncthreads();
    if (!s_last) return;
    __threadfence();   // acquire: see other CTAs' g_pmax writes

    if (t < 32) {
        float m = -1000.f;
#pragma unroll
        for (int ci2 = 0; ci2 < NSPL; ci2++)
            m = fmaxf(m, g_pmax[(b * NSPL + ci2) * LQ_ + t]);
        float term = qmask[b * LQ_ + t] ? m : 0.f;
#pragma unroll
        for (int o = 16; o >= 1; o >>= 1)
            term += __shfl_xor_sync(0xffffffffu, term, o);
        if (t == 0) {
            float w_  = 1.f / (1.f + expf(-merger[0]));
            float cls = g_cls[b] * w_;
            float ts  = term * (1.f - w_);
            out[b]          = cls + ts;
            out[B_ + b]     = cls;
            out[2 * B_ + b] = ts;
            g_cnt[b] = 0;   // reset for next graph replay
        }
    }
}

extern "C" void kernel_launch(void* const* d_in, const int* in_sizes, int n_in,
                              void* d_out, int out_size)
{
    const float* query_hidden = (const float*)d_in[0];
    const float* doc_hidden   = (const float*)d_in[1];
    const int*   query_mask   = (const int*)  d_in[2];
    const int*   doc_mask     = (const int*)  d_in[3];
    const float* W_comp       = (const float*)d_in[4];
    const float* b_comp       = (const float*)d_in[5];
    const float* w_stop       = (const float*)d_in[6];
    const float* b_stop       = (const float*)d_in[7];
    const float* score_merger = (const float*)d_in[8];
    float* out = (float*)d_out;

    cudaFuncSetAttribute(gemm_all,
                         cudaFuncAttributeMaxDynamicSharedMemorySize, GEMM_SMEM);
    cudaFuncSetAttribute(score_fused,
                         cudaFuncAttributeMaxDynamicSharedMemorySize, SP_SMEM);

    prep_all<<<224, 256>>>(W_comp, query_hidden, doc_hidden);
    gemm_all<<<QBLK + DBLK, 256, GEMM_SMEM>>>(
        query_hidden, doc_hidden, b_comp, w_stop, b_stop,
        query_mask, doc_mask);
    score_fused<<<B_ * NSPL, 256, SP_SMEM>>>(
        doc_mask, query_mask, score_merger, out);
}

// round 16
// speedup vs baseline: 1.2830x; 1.1860x over previous
#include <cuda_runtime.h>
#include <cuda_fp16.h>
#include <math.h>
#include <stdint.h>

#define B_  128
#define LQ_ 32
#define LD_ 512
#define H_  768
#define C_  128
#define KCH 32
#define NCH (H_ / KCH)   // 24 K-chunks
#define AP  40           // A [row][k] pad (fp32) — conflict-free LDS.64
#define BPh 40           // B [col][k] pad (fp16)
#define STG 3            // cp.async pipeline stages
#define NSPL 8           // score split-K chunks (512/64)
#define KROWS 64         // k-rows per score CTA
#define QBLK (B_ * LQ_ / 128)    // 32 query gemm blocks
#define DBLK (B_ * LD_ / 128)    // 512 doc gemm blocks

// Scratch (__device__ globals: allocation-free rule)
__device__ __half g_dvecs[B_ * LD_ * C_];   // 16.7 MB
__device__ __half g_qvecs[B_ * LQ_ * C_];   // 1 MB
__device__ __half g_Wth[C_ * H_];           // W_comp transposed, fp16
__device__ float  g_pmax[B_ * NSPL * LQ_];  // split-K partial maxima
__device__ float  g_cls[B_];                // CLS dot per batch
__device__ int    g_cnt[B_];                // zero-init; self-resetting

__device__ __forceinline__ uint32_t smem_u32(const void* p) {
    uint32_t a;
    asm("{ .reg .u64 t; cvta.to.shared.u64 t, %1; cvt.u32.u64 %0, t; }"
        : "=r"(a) : "l"(p));
    return a;
}
__device__ __forceinline__ void cp16(void* dst, const void* src) {
    asm volatile("cp.async.cg.shared.global [%0], [%1], 16;"
                 :: "r"(smem_u32(dst)), "l"(src));
}
#define CP_COMMIT() asm volatile("cp.async.commit_group;" ::: "memory")
#define CP_WAIT1()  asm volatile("cp.async.wait_group 1;" ::: "memory")

__device__ __forceinline__ uint32_t h2u(float x, float y) {
    __half2 h = __floats2half2_rn(x, y);
    return *(uint32_t*)&h;
}

__device__ __forceinline__ void mma_f16(float c[4], uint32_t a0, uint32_t a1,
                                        uint32_t a2, uint32_t a3,
                                        uint32_t b0, uint32_t b1) {
    asm volatile(
        "mma.sync.aligned.m16n8k16.row.col.f32.f16.f16.f32 "
        "{%0,%1,%2,%3}, {%4,%5,%6,%7}, {%8,%9}, {%0,%1,%2,%3};"
        : "+f"(c[0]), "+f"(c[1]), "+f"(c[2]), "+f"(c[3])
        : "r"(a0), "r"(a1), "r"(a2), "r"(a3), "r"(b0), "r"(b1));
}

// ---------------------------------------------------------------------------
// Prep: blocks 0..95 tile-transpose W_comp [H,C] -> g_Wth [C,H] fp16;
//       blocks 96..223 compute CLS dots -> g_cls[b]
// ---------------------------------------------------------------------------
__global__ void prep_all(const float* __restrict__ W,
                         const float* __restrict__ qh,
                         const float* __restrict__ dhid)
{
    if (blockIdx.x < 96) {
        __shared__ float tile[32][33];
        const int r0 = (blockIdx.x >> 2) * 32;
        const int c0 = (blockIdx.x & 3) * 32;
        const int t  = threadIdx.x;
        const int rr = t >> 5, cc = t & 31;
#pragma unroll
        for (int u = 0; u < 4; u++) {
            int r = rr + 8 * u;
            tile[cc][r] = W[(size_t)(r0 + r) * C_ + c0 + cc];
        }
        __syncthreads();
#pragma unroll
        for (int u = 0; u < 4; u++) {
            int c = rr + 8 * u;
            g_Wth[(size_t)(c0 + c) * H_ + r0 + cc] = __float2half_rn(tile[c][cc]);
        }
    } else {
        __shared__ float s_red[256];
        const int b = blockIdx.x - 96;
        const int t = threadIdx.x;
        const float* qp = qh   + (size_t)b * LQ_ * H_;
        const float* dp = dhid + (size_t)b * LD_ * H_;
        float p = 0.f;
        for (int h = t; h < H_; h += 256) p += qp[h] * dp[h];
        s_red[t] = p;
        __syncthreads();
        for (int s = 128; s > 0; s >>= 1) {
            if (t < s) s_red[t] += s_red[t + s];
            __syncthreads();
        }
        if (t == 0) g_cls[b] = s_red[0];
    }
}

// ---------------------------------------------------------------------------
// Merged projection GEMM (query blocks 0..31, doc blocks 32..543).
// 128x128 tile/CTA, 8 warps = 4m x 2n (warp m32 x n64).
// 3-stage cp.async pipeline, mma.sync fp16, fp32 accum, AP=40 (conflict-free).
// Doc: fused importance gating + dm mask -> g_dvecs; query: qm -> g_qvecs.
// ---------------------------------------------------------------------------
#define A_BYTES (128 * AP * 4)
#define B_BYTES (128 * BPh * 2)
#define STAGE_BYTES (A_BYTES + B_BYTES)
#define GEMM_SMEM (STG * STAGE_BYTES)   // 92160 B; x2 CTAs = 184320 <= 233472

__global__ void __launch_bounds__(256, 2) gemm_all(
    const float* __restrict__ Xq,
    const float* __restrict__ Xd,
    const float* __restrict__ bcomp,
    const float* __restrict__ wstop,
    const float* __restrict__ bstop,
    const int*   __restrict__ qmask,
    const int*   __restrict__ dmask)
{
    extern __shared__ char smg[];

    const bool isq = blockIdx.x < QBLK;
    const int  blk = isq ? blockIdx.x : blockIdx.x - QBLK;
    const float* X    = isq ? Xq : Xd;
    const int*   mask = isq ? qmask : dmask;

    const int t    = threadIdx.x;
    const int lane = t & 31;
    const int w    = t >> 5;
    const int wm   = w >> 1, wn = w & 1;
    const int g    = lane >> 2, tig = lane & 3;
    const int Rl   = wm * 32, Cl = wn * 64;
    const int row0 = blk * 128;

    // A staging: row = t>>3 (+32u), col quad = (t&7)*4 floats
    const int sar = t >> 3;
    const int sak = (t & 7) * 4;
    const float* Xp = X + (size_t)(row0 + sar) * H_ + sak;

    float acc[2][8][4];
#pragma unroll
    for (int mt = 0; mt < 2; mt++)
#pragma unroll
        for (int nt = 0; nt < 8; nt++)
#pragma unroll
            for (int x = 0; x < 4; x++) acc[mt][nt][x] = 0.f;

    // ---- prologue: stage chunks 0,1 ----
#pragma unroll
    for (int s = 0; s < 2; s++) {
        float*  As = (float*)(smg + s * STAGE_BYTES);
        __half* Bs = (__half*)(smg + s * STAGE_BYTES + A_BYTES);
        const int kt = s * KCH;
#pragma unroll
        for (int u = 0; u < 4; u++)
            cp16(&As[(sar + 32 * u) * AP + sak], Xp + (size_t)(32 * u) * H_ + kt);
#pragma unroll
        for (int u = 0; u < 2; u++) {
            int i  = t + u * 256;
            int cb = i >> 2;
            int k8 = (i & 3) * 8;
            cp16(&Bs[cb * BPh + k8], g_Wth + (size_t)cb * H_ + kt + k8);
        }
        CP_COMMIT();
    }

    int snext = 2;
    for (int ch = 0; ch < NCH; ch++) {
        CP_WAIT1();
        __syncthreads();

        if (ch + 2 < NCH) {
            float*  As = (float*)(smg + snext * STAGE_BYTES);
            __half* Bs = (__half*)(smg + snext * STAGE_BYTES + A_BYTES);
            const int kt = (ch + 2) * KCH;
#pragma unroll
            for (int u = 0; u < 4; u++)
                cp16(&As[(sar + 32 * u) * AP + sak],
                     Xp + (size_t)(32 * u) * H_ + kt);
#pragma unroll
            for (int u = 0; u < 2; u++) {
                int i  = t + u * 256;
                int cb = i >> 2;
                int k8 = (i & 3) * 8;
                cp16(&Bs[cb * BPh + k8], g_Wth + (size_t)cb * H_ + kt + k8);
            }
            CP_COMMIT();
            snext = (snext + 1 == STG) ? 0 : snext + 1;
        } else {
            CP_COMMIT();
        }

        const int sc = ch % STG;
        const float*  As = (const float*)(smg + sc * STAGE_BYTES);
        const __half* Bs = (const __half*)(smg + sc * STAGE_BYTES + A_BYTES);

#pragma unroll
        for (int ks = 0; ks < 2; ks++) {
            const int k0 = ks * 16;
            uint32_t a[2][4];
#pragma unroll
            for (int mt = 0; mt < 2; mt++) {
                int r = Rl + mt * 16 + g;
                float2 f0 = *(const float2*)&As[r * AP + k0 + 2 * tig];
                float2 f1 = *(const float2*)&As[(r + 8) * AP + k0 + 2 * tig];
                float2 f2 = *(const float2*)&As[r * AP + k0 + 8 + 2 * tig];
                float2 f3 = *(const float2*)&As[(r + 8) * AP + k0 + 8 + 2 * tig];
                a[mt][0] = h2u(f0.x, f0.y);
                a[mt][1] = h2u(f1.x, f1.y);
                a[mt][2] = h2u(f2.x, f2.y);
                a[mt][3] = h2u(f3.x, f3.y);
            }
#pragma unroll
            for (int nt = 0; nt < 8; nt++) {
                int c = Cl + nt * 8 + g;
                uint32_t b0 = *(const uint32_t*)&Bs[c * BPh + k0 + 2 * tig];
                uint32_t b1 = *(const uint32_t*)&Bs[c * BPh + k0 + 8 + 2 * tig];
                mma_f16(acc[0][nt], a[0][0], a[0][1], a[0][2], a[0][3], b0, b1);
                mma_f16(acc[1][nt], a[1][0], a[1][1], a[1][2], a[1][3], b0, b1);
            }
        }
    }
    __syncthreads();

    // ---- Epilogue ----
    float bb[8][2];
#pragma unroll
    for (int nt = 0; nt < 8; nt++) {
        int c0 = Cl + nt * 8 + 2 * tig;
        bb[nt][0] = bcomp[c0];
        bb[nt][1] = bcomp[c0 + 1];
    }

    float (*spart)[2] = (float(*)[2])smg;        // 128 x 2 partials
    float* sscale     = (float*)smg + 256;       // 128 scales

    if (!isq) {
        float ws[8][2];
#pragma unroll
        for (int nt = 0; nt < 8; nt++) {
            int c0 = Cl + nt * 8 + 2 * tig;
            ws[nt][0] = wstop[c0];
            ws[nt][1] = wstop[c0 + 1];
        }
        float p[2][2] = {{0.f, 0.f}, {0.f, 0.f}};
#pragma unroll
        for (int mt = 0; mt < 2; mt++)
#pragma unroll
            for (int nt = 0; nt < 8; nt++) {
                p[mt][0] += (acc[mt][nt][0] + bb[nt][0]) * ws[nt][0]
                          + (acc[mt][nt][1] + bb[nt][1]) * ws[nt][1];
                p[mt][1] += (acc[mt][nt][2] + bb[nt][0]) * ws[nt][0]
                          + (acc[mt][nt][3] + bb[nt][1]) * ws[nt][1];
            }
#pragma unroll
        for (int mt = 0; mt < 2; mt++)
#pragma unroll
            for (int h = 0; h < 2; h++) {
                float v = p[mt][h];
                v += __shfl_xor_sync(0xffffffffu, v, 1);
                v += __shfl_xor_sync(0xffffffffu, v, 2);
                p[mt][h] = v;
            }
        if (tig == 0) {
#pragma unroll
            for (int mt = 0; mt < 2; mt++)
#pragma unroll
                for (int h = 0; h < 2; h++)
                    spart[Rl + mt * 16 + g + 8 * h][wn] = p[mt][h];
        }
        __syncthreads();
        if (t < 128) {
            float pp = spart[t][0] + spart[t][1] + bstop[0];
            sscale[t] = fmaxf(pp, 0.f) * (float)mask[row0 + t];
        }
        __syncthreads();
    } else {
        if (t < 128) sscale[t] = (float)mask[row0 + t];
        __syncthreads();
    }

    __half* OUT = isq ? g_qvecs : g_dvecs;
#pragma unroll
    for (int mt = 0; mt < 2; mt++)
#pragma unroll
        for (int h = 0; h < 2; h++) {
            int lrow = Rl + mt * 16 + g + 8 * h;
            float s  = sscale[lrow];
            int row  = row0 + lrow;
#pragma unroll
            for (int nt = 0; nt < 8; nt++) {
                int c0 = Cl + nt * 8 + 2 * tig;
                uint32_t hv = h2u((acc[mt][nt][2 * h + 0] + bb[nt][0]) * s,
                                  (acc[mt][nt][2 * h + 1] + bb[nt][1]) * s);
                *(uint32_t*)(OUT + (size_t)row * C_ + c0) = hv;
            }
        }
}

// ---------------------------------------------------------------------------
// Fused split-K scoring: CTA (b, ci) computes masked max over 64 k-rows
// -> g_pmax; the LAST CTA per batch (atomic counter) merges, adds CLS,
// applies sigmoid merge, writes output, and resets the counter.
// ---------------------------------------------------------------------------
#define QPh 136
#define SP_SMEM ((32 * QPh + KROWS * QPh) * 2 + 128 * 4 + KROWS * 4)

__global__ void __launch_bounds__(256) score_fused(
    const int* __restrict__ dmask,
    const int* __restrict__ qmask,
    const float* __restrict__ merger,
    float* __restrict__ out)
{
    extern __shared__ char smc[];
    __half* qs   = (__half*)smc;                        // 32 * QPh
    __half* ds   = qs + 32 * QPh;                       // KROWS * QPh
    float*  redm = (float*)(ds + KROWS * QPh);          // 128 floats
    int*    dmch = (int*)(redm + 128);                  // KROWS ints
    __shared__ int s_last;

    const int b    = blockIdx.x >> 3;
    const int ci   = blockIdx.x & 7;
    const int k0g  = ci * KROWS;
    const int t    = threadIdx.x;
    const int lane = t & 31;
    const int w    = t >> 5;
    const int g    = lane >> 2, tig = lane & 3;
    const int wq   = w & 1;    // q half (16 rows)
    const int wk   = w >> 1;   // k group (16 rows)

    // Stage q_vecs [32 x 128] fp16
#pragma unroll
    for (int u = 0; u < 2; u++) {
        int i  = t + u * 256;
        int q  = i >> 4;
        int c8 = (i & 15) * 8;
        *(uint4*)&qs[q * QPh + c8] = *(const uint4*)(
            g_qvecs + (size_t)b * LQ_ * C_ + (size_t)q * C_ + c8);
    }
    // Stage d chunk [64 x 128] fp16
#pragma unroll
    for (int u = 0; u < 4; u++) {
        int i  = t + u * 256;
        int k  = i >> 4;
        int c8 = (i & 15) * 8;
        *(uint4*)&ds[k * QPh + c8] = *(const uint4*)(
            g_dvecs + (size_t)b * LD_ * C_ + (size_t)(k0g + k) * C_ + c8);
    }
    if (t < KROWS) dmch[t] = dmask[b * LD_ + k0g + t];
    __syncthreads();

    float acc[2][4];
#pragma unroll
    for (int nt = 0; nt < 2; nt++)
#pragma unroll
        for (int x = 0; x < 4; x++) acc[nt][x] = 0.f;

#pragma unroll
    for (int cs = 0; cs < 8; cs++) {
        const int c0 = cs * 16;
        uint32_t a0 = *(const uint32_t*)&qs[(wq * 16 + g) * QPh + c0 + 2 * tig];
        uint32_t a1 = *(const uint32_t*)&qs[(wq * 16 + g + 8) * QPh + c0 + 2 * tig];
        uint32_t a2 = *(const uint32_t*)&qs[(wq * 16 + g) * QPh + c0 + 8 + 2 * tig];
        uint32_t a3 = *(const uint32_t*)&qs[(wq * 16 + g + 8) * QPh + c0 + 8 + 2 * tig];
#pragma unroll
        for (int nt = 0; nt < 2; nt++) {
            int n = wk * 16 + nt * 8 + g;
            uint32_t b0 = *(const uint32_t*)&ds[n * QPh + c0 + 2 * tig];
            uint32_t b1 = *(const uint32_t*)&ds[n * QPh + c0 + 8 + 2 * tig];
            mma_f16(acc[nt], a0, a1, a2, a3, b0, b1);
        }
    }

    float mx0 = -1000.f, mx1 = -1000.f;
#pragma unroll
    for (int nt = 0; nt < 2; nt++) {
        int n0 = wk * 16 + nt * 8 + 2 * tig;
        if (dmch[n0]) {
            mx0 = fmaxf(mx0, acc[nt][0]);
            mx1 = fmaxf(mx1, acc[nt][2]);
        }
        if (dmch[n0 + 1]) {
            mx0 = fmaxf(mx0, acc[nt][1]);
            mx1 = fmaxf(mx1, acc[nt][3]);
        }
    }
    mx0 = fmaxf(mx0, __shfl_xor_sync(0xffffffffu, mx0, 1));
    mx0 = fmaxf(mx0, __shfl_xor_sync(0xffffffffu, mx0, 2));
    mx1 = fmaxf(mx1, __shfl_xor_sync(0xffffffffu, mx1, 1));
    mx1 = fmaxf(mx1, __shfl_xor_sync(0xffffffffu, mx1, 2));
    __syncthreads();
    if (tig == 0) {
        redm[(wq * 16 + g) * 4 + wk]     = mx0;
        redm[(wq * 16 + g + 8) * 4 + wk] = mx1;
    }
    __syncthreads();

    if (t < 32) {
        float m = fmaxf(fmaxf(redm[t * 4 + 0], redm[t * 4 + 1]),
                        fmaxf(redm[t * 4 + 2], redm[t * 4 + 3]));
        g_pmax[(b * NSPL + ci) * LQ_ + t] = m;
    }

    // ---- last-CTA merge ----
    __threadfence();
    if (t == 0) {
        int old = atomicAdd(&g_cnt[b], 1);
        s_last = (old == NSPL - 1);
    }
    __syncthreads();
    if (!s_last) return;
    __threadfence();   // acquire: see other CTAs' g_pmax writes

    if (t < 32) {
        float m = -1000.f;
#pragma unroll
        for (int ci2 = 0; ci2 < NSPL; ci2++)
            m = fmaxf(m, g_pmax[(b * NSPL + ci2) * LQ_ + t]);
        float term = qmask[b * LQ_ + t] ? m : 0.f;
#pragma unroll
        for (int o = 16; o >= 1; o >>= 1)
            term += __shfl_xor_sync(0xffffffffu, term, o);
        if (t == 0) {
            float w_  = 1.f / (1.f + expf(-merger[0]));
            float cls = g_cls[b] * w_;
            float ts  = term * (1.f - w_);
            out[b]          = cls + ts;
            out[B_ + b]     = cls;
            out[2 * B_ + b] = ts;
            g_cnt[b] = 0;   // reset for next graph replay
        }
    }
}

extern "C" void kernel_launch(void* const* d_in, const int* in_sizes, int n_in,
                              void* d_out, int out_size)
{
    const float* query_hidden = (const float*)d_in[0];
    const float* doc_hidden   = (const float*)d_in[1];
    const int*   query_mask   = (const int*)  d_in[2];
    const int*   doc_mask     = (const int*)  d_in[3];
    const float* W_comp       = (const float*)d_in[4];
    const float* b_comp       = (const float*)d_in[5];
    const float* w_stop       = (const float*)d_in[6];
    const float* b_stop       = (const float*)d_in[7];
    const float* score_merger = (const float*)d_in[8];
    float* out = (float*)d_out;

    cudaFuncSetAttribute(gemm_all,
                         cudaFuncAttributeMaxDynamicSharedMemorySize, GEMM_SMEM);
    cudaFuncSetAttribute(score_fused,
                         cudaFuncAttributeMaxDynamicSharedMemorySize, SP_SMEM);

    prep_all<<<224, 256>>>(W_comp, query_hidden, doc_hidden);
    gemm_all<<<QBLK + DBLK, 256, GEMM_SMEM>>>(
        query_hidden, doc_hidden, b_comp, w_stop, b_stop,
        query_mask, doc_mask);
    score_fused<<<B_ * NSPL, 256, SP_SMEM>>>(
        doc_mask, query_mask, score_merger, out);
}

// round 17
// speedup vs baseline: 1.3081x; 1.0196x over previous
#include <cuda_runtime.h>
#include <cuda_fp16.h>
#include <math.h>
#include <stdint.h>

#define B_  128
#define LQ_ 32
#define LD_ 512
#define H_  768
#define C_  128
#define KCH 32
#define NCH (H_ / KCH)   // 24 K-chunks
#define AP  40           // A [row][k] pad (fp32) — conflict-free LDS.64
#define BPh 40           // B [col][k] pad (fp16)
#define STG 3            // cp.async pipeline stages
#define NSPL 8           // score split-K chunks (512/64)
#define KROWS 64         // k-rows per score CTA
#define QBLK (B_ * LQ_ / 128)    // 32 query gemm blocks
#define DBLK (B_ * LD_ / 128)    // 512 doc gemm blocks

// Scratch (__device__ globals: allocation-free rule)
__device__ __half g_dvecs[B_ * LD_ * C_];   // 16.7 MB
__device__ __half g_qvecs[B_ * LQ_ * C_];   // 1 MB
__device__ __half g_Wth[C_ * H_];           // W_comp transposed, fp16
__device__ float  g_pmax[B_ * NSPL * LQ_];  // split-K partial maxima
__device__ int    g_cnt[B_];                // zero-init; self-resetting

__device__ __forceinline__ uint32_t smem_u32(const void* p) {
    uint32_t a;
    asm("{ .reg .u64 t; cvta.to.shared.u64 t, %1; cvt.u32.u64 %0, t; }"
        : "=r"(a) : "l"(p));
    return a;
}
__device__ __forceinline__ void cp16(void* dst, const void* src) {
    asm volatile("cp.async.cg.shared.global [%0], [%1], 16;"
                 :: "r"(smem_u32(dst)), "l"(src));
}
#define CP_COMMIT() asm volatile("cp.async.commit_group;" ::: "memory")
#define CP_WAIT1()  asm volatile("cp.async.wait_group 1;" ::: "memory")

__device__ __forceinline__ uint32_t h2u(float x, float y) {
    __half2 h = __floats2half2_rn(x, y);
    return *(uint32_t*)&h;
}

__device__ __forceinline__ void mma_f16(float c[4], uint32_t a0, uint32_t a1,
                                        uint32_t a2, uint32_t a3,
                                        uint32_t b0, uint32_t b1) {
    asm volatile(
        "mma.sync.aligned.m16n8k16.row.col.f32.f16.f16.f32 "
        "{%0,%1,%2,%3}, {%4,%5,%6,%7}, {%8,%9}, {%0,%1,%2,%3};"
        : "+f"(c[0]), "+f"(c[1]), "+f"(c[2]), "+f"(c[3])
        : "r"(a0), "r"(a1), "r"(a2), "r"(a3), "r"(b0), "r"(b1));
}
__device__ __forceinline__ void ldm_x4(uint32_t& r0, uint32_t& r1,
                                       uint32_t& r2, uint32_t& r3,
                                       uint32_t addr) {
    asm volatile(
        "ldmatrix.sync.aligned.m8n8.x4.shared.b16 {%0,%1,%2,%3}, [%4];"
        : "=r"(r0), "=r"(r1), "=r"(r2), "=r"(r3) : "r"(addr));
}

// ---------------------------------------------------------------------------
// Prep: 96 blocks tile-transpose W_comp [H,C] -> g_Wth [C,H] fp16
// ---------------------------------------------------------------------------
__global__ void prep_w(const float* __restrict__ W) {
    __shared__ float tile[32][33];
    const int r0 = (blockIdx.x >> 2) * 32;
    const int c0 = (blockIdx.x & 3) * 32;
    const int t  = threadIdx.x;
    const int rr = t >> 5, cc = t & 31;
#pragma unroll
    for (int u = 0; u < 4; u++) {
        int r = rr + 8 * u;
        tile[cc][r] = W[(size_t)(r0 + r) * C_ + c0 + cc];
    }
    __syncthreads();
#pragma unroll
    for (int u = 0; u < 4; u++) {
        int c = rr + 8 * u;
        g_Wth[(size_t)(c0 + c) * H_ + r0 + cc] = __float2half_rn(tile[c][cc]);
    }
}

// ---------------------------------------------------------------------------
// Merged projection GEMM (query blocks 0..31, doc blocks 32..543).
// 128x128 tile/CTA, 8 warps = 4m x 2n (warp m32 x n64).
// 3-stage cp.async pipeline, mma.sync fp16, fp32 accum, AP=40 conflict-free,
// B fragments via ldmatrix.x4 (4 tiles = nt-pair x both k-halves).
// Doc: fused importance gating + dm mask -> g_dvecs; query: qm -> g_qvecs.
// ---------------------------------------------------------------------------
#define A_BYTES (128 * AP * 4)
#define B_BYTES (128 * BPh * 2)
#define STAGE_BYTES (A_BYTES + B_BYTES)
#define GEMM_SMEM (STG * STAGE_BYTES)   // 92160 B; x2 CTAs fits

__global__ void __launch_bounds__(256, 2) gemm_all(
    const float* __restrict__ Xq,
    const float* __restrict__ Xd,
    const float* __restrict__ bcomp,
    const float* __restrict__ wstop,
    const float* __restrict__ bstop,
    const int*   __restrict__ qmask,
    const int*   __restrict__ dmask)
{
    extern __shared__ char smg[];

    const bool isq = blockIdx.x < QBLK;
    const int  blk = isq ? blockIdx.x : blockIdx.x - QBLK;
    const float* X    = isq ? Xq : Xd;
    const int*   mask = isq ? qmask : dmask;

    const int t    = threadIdx.x;
    const int lane = t & 31;
    const int w    = t >> 5;
    const int wm   = w >> 1, wn = w & 1;
    const int g    = lane >> 2, tig = lane & 3;
    const int Rl   = wm * 32, Cl = wn * 64;
    const int row0 = blk * 128;

    // ldmatrix per-lane address component (in halfs, within B stage):
    // tile layout per (p, ks): lanes 0-7 -> (nt=2p, kh0), 8-15 -> (2p, kh1),
    // 16-23 -> (2p+1, kh0), 24-31 -> (2p+1, kh1)
    const int lrow  = lane & 7;
    const int lkh   = (lane >> 3) & 1;
    const int lnt   = lane >> 4;
    const uint32_t bfrag_off =
        (uint32_t)((Cl + lnt * 8 + lrow) * BPh + lkh * 8) * 2;   // bytes

    // A staging: row = t>>3 (+32u), col quad = (t&7)*4 floats
    const int sar = t >> 3;
    const int sak = (t & 7) * 4;
    const float* Xp = X + (size_t)(row0 + sar) * H_ + sak;

    float acc[2][8][4];
#pragma unroll
    for (int mt = 0; mt < 2; mt++)
#pragma unroll
        for (int nt = 0; nt < 8; nt++)
#pragma unroll
            for (int x = 0; x < 4; x++) acc[mt][nt][x] = 0.f;

    // ---- prologue: stage chunks 0,1 ----
#pragma unroll
    for (int s = 0; s < 2; s++) {
        float*  As = (float*)(smg + s * STAGE_BYTES);
        __half* Bs = (__half*)(smg + s * STAGE_BYTES + A_BYTES);
        const int kt = s * KCH;
#pragma unroll
        for (int u = 0; u < 4; u++)
            cp16(&As[(sar + 32 * u) * AP + sak], Xp + (size_t)(32 * u) * H_ + kt);
#pragma unroll
        for (int u = 0; u < 2; u++) {
            int i  = t + u * 256;
            int cb = i >> 2;
            int k8 = (i & 3) * 8;
            cp16(&Bs[cb * BPh + k8], g_Wth + (size_t)cb * H_ + kt + k8);
        }
        CP_COMMIT();
    }

    int snext = 2;
    for (int ch = 0; ch < NCH; ch++) {
        CP_WAIT1();
        __syncthreads();

        if (ch + 2 < NCH) {
            float*  As = (float*)(smg + snext * STAGE_BYTES);
            __half* Bs = (__half*)(smg + snext * STAGE_BYTES + A_BYTES);
            const int kt = (ch + 2) * KCH;
#pragma unroll
            for (int u = 0; u < 4; u++)
                cp16(&As[(sar + 32 * u) * AP + sak],
                     Xp + (size_t)(32 * u) * H_ + kt);
#pragma unroll
            for (int u = 0; u < 2; u++) {
                int i  = t + u * 256;
                int cb = i >> 2;
                int k8 = (i & 3) * 8;
                cp16(&Bs[cb * BPh + k8], g_Wth + (size_t)cb * H_ + kt + k8);
            }
            CP_COMMIT();
            snext = (snext + 1 == STG) ? 0 : snext + 1;
        } else {
            CP_COMMIT();
        }

        const int sc = ch % STG;
        const float*   As = (const float*)(smg + sc * STAGE_BYTES);
        const uint32_t Bbase = smem_u32(smg + sc * STAGE_BYTES + A_BYTES)
                             + bfrag_off;

#pragma unroll
        for (int ks = 0; ks < 2; ks++) {
            const int k0 = ks * 16;
            uint32_t a[2][4];
#pragma unroll
            for (int mt = 0; mt < 2; mt++) {
                int r = Rl + mt * 16 + g;
                float2 f0 = *(const float2*)&As[r * AP + k0 + 2 * tig];
                float2 f1 = *(const float2*)&As[(r + 8) * AP + k0 + 2 * tig];
                float2 f2 = *(const float2*)&As[r * AP + k0 + 8 + 2 * tig];
                float2 f3 = *(const float2*)&As[(r + 8) * AP + k0 + 8 + 2 * tig];
                a[mt][0] = h2u(f0.x, f0.y);
                a[mt][1] = h2u(f1.x, f1.y);
                a[mt][2] = h2u(f2.x, f2.y);
                a[mt][3] = h2u(f3.x, f3.y);
            }
#pragma unroll
            for (int p = 0; p < 4; p++) {
                uint32_t b00, b01, b10, b11;   // (nt=2p: b0,b1), (nt=2p+1: b0,b1)
                ldm_x4(b00, b01, b10, b11,
                       Bbase + (uint32_t)(p * 16 * BPh + k0) * 2);
                mma_f16(acc[0][2 * p],     a[0][0], a[0][1], a[0][2], a[0][3], b00, b01);
                mma_f16(acc[1][2 * p],     a[1][0], a[1][1], a[1][2], a[1][3], b00, b01);
                mma_f16(acc[0][2 * p + 1], a[0][0], a[0][1], a[0][2], a[0][3], b10, b11);
                mma_f16(acc[1][2 * p + 1], a[1][0], a[1][1], a[1][2], a[1][3], b10, b11);
            }
        }
    }
    __syncthreads();

    // ---- Epilogue ----
    float bb[8][2];
#pragma unroll
    for (int nt = 0; nt < 8; nt++) {
        int c0 = Cl + nt * 8 + 2 * tig;
        bb[nt][0] = bcomp[c0];
        bb[nt][1] = bcomp[c0 + 1];
    }

    float (*spart)[2] = (float(*)[2])smg;        // 128 x 2 partials
    float* sscale     = (float*)smg + 256;       // 128 scales

    if (!isq) {
        float ws[8][2];
#pragma unroll
        for (int nt = 0; nt < 8; nt++) {
            int c0 = Cl + nt * 8 + 2 * tig;
            ws[nt][0] = wstop[c0];
            ws[nt][1] = wstop[c0 + 1];
        }
        float p[2][2] = {{0.f, 0.f}, {0.f, 0.f}};
#pragma unroll
        for (int mt = 0; mt < 2; mt++)
#pragma unroll
            for (int nt = 0; nt < 8; nt++) {
                p[mt][0] += (acc[mt][nt][0] + bb[nt][0]) * ws[nt][0]
                          + (acc[mt][nt][1] + bb[nt][1]) * ws[nt][1];
                p[mt][1] += (acc[mt][nt][2] + bb[nt][0]) * ws[nt][0]
                          + (acc[mt][nt][3] + bb[nt][1]) * ws[nt][1];
            }
#pragma unroll
        for (int mt = 0; mt < 2; mt++)
#pragma unroll
            for (int h = 0; h < 2; h++) {
                float v = p[mt][h];
                v += __shfl_xor_sync(0xffffffffu, v, 1);
                v += __shfl_xor_sync(0xffffffffu, v, 2);
                p[mt][h] = v;
            }
        if (tig == 0) {
#pragma unroll
            for (int mt = 0; mt < 2; mt++)
#pragma unroll
                for (int h = 0; h < 2; h++)
                    spart[Rl + mt * 16 + g + 8 * h][wn] = p[mt][h];
        }
        __syncthreads();
        if (t < 128) {
            float pp = spart[t][0] + spart[t][1] + bstop[0];
            sscale[t] = fmaxf(pp, 0.f) * (float)mask[row0 + t];
        }
        __syncthreads();
    } else {
        if (t < 128) sscale[t] = (float)mask[row0 + t];
        __syncthreads();
    }

    __half* OUT = isq ? g_qvecs : g_dvecs;
#pragma unroll
    for (int mt = 0; mt < 2; mt++)
#pragma unroll
        for (int h = 0; h < 2; h++) {
            int lrow2 = Rl + mt * 16 + g + 8 * h;
            float s   = sscale[lrow2];
            int row   = row0 + lrow2;
#pragma unroll
            for (int nt = 0; nt < 8; nt++) {
                int c0 = Cl + nt * 8 + 2 * tig;
                uint32_t hv = h2u((acc[mt][nt][2 * h + 0] + bb[nt][0]) * s,
                                  (acc[mt][nt][2 * h + 1] + bb[nt][1]) * s);
                *(uint32_t*)(OUT + (size_t)row * C_ + c0) = hv;
            }
        }
}

// ---------------------------------------------------------------------------
// Fused split-K scoring: CTA (b, ci) computes masked max over 64 k-rows
// -> g_pmax; the LAST CTA per batch computes the CLS dot (256 threads),
// merges partial maxima, applies sigmoid merge, writes output, resets counter.
// ---------------------------------------------------------------------------
#define QPh 136
#define SP_SMEM ((32 * QPh + KROWS * QPh) * 2 + 128 * 4 + KROWS * 4)

__global__ void __launch_bounds__(256) score_fused(
    const float* __restrict__ qh,
    const float* __restrict__ dhid,
    const int* __restrict__ dmask,
    const int* __restrict__ qmask,
    const float* __restrict__ merger,
    float* __restrict__ out)
{
    extern __shared__ char smc[];
    __half* qs   = (__half*)smc;                        // 32 * QPh
    __half* ds   = qs + 32 * QPh;                       // KROWS * QPh
    float*  redm = (float*)(ds + KROWS * QPh);          // 128 floats
    int*    dmch = (int*)(redm + 128);                  // KROWS ints
    __shared__ int   s_last;
    __shared__ float s_red[256];

    const int b    = blockIdx.x >> 3;
    const int ci   = blockIdx.x & 7;
    const int k0g  = ci * KROWS;
    const int t    = threadIdx.x;
    const int lane = t & 31;
    const int w    = t >> 5;
    const int g    = lane >> 2, tig = lane & 3;
    const int wq   = w & 1;    // q half (16 rows)
    const int wk   = w >> 1;   // k group (16 rows)

    // Stage q_vecs [32 x 128] fp16
#pragma unroll
    for (int u = 0; u < 2; u++) {
        int i  = t + u * 256;
        int q  = i >> 4;
        int c8 = (i & 15) * 8;
        *(uint4*)&qs[q * QPh + c8] = *(const uint4*)(
            g_qvecs + (size_t)b * LQ_ * C_ + (size_t)q * C_ + c8);
    }
    // Stage d chunk [64 x 128] fp16
#pragma unroll
    for (int u = 0; u < 4; u++) {
        int i  = t + u * 256;
        int k  = i >> 4;
        int c8 = (i & 15) * 8;
        *(uint4*)&ds[k * QPh + c8] = *(const uint4*)(
            g_dvecs + (size_t)b * LD_ * C_ + (size_t)(k0g + k) * C_ + c8);
    }
    if (t < KROWS) dmch[t] = dmask[b * LD_ + k0g + t];
    __syncthreads();

    float acc[2][4];
#pragma unroll
    for (int nt = 0; nt < 2; nt++)
#pragma unroll
        for (int x = 0; x < 4; x++) acc[nt][x] = 0.f;

#pragma unroll
    for (int cs = 0; cs < 8; cs++) {
        const int c0 = cs * 16;
        uint32_t a0 = *(const uint32_t*)&qs[(wq * 16 + g) * QPh + c0 + 2 * tig];
        uint32_t a1 = *(const uint32_t*)&qs[(wq * 16 + g + 8) * QPh + c0 + 2 * tig];
        uint32_t a2 = *(const uint32_t*)&qs[(wq * 16 + g) * QPh + c0 + 8 + 2 * tig];
        uint32_t a3 = *(const uint32_t*)&qs[(wq * 16 + g + 8) * QPh + c0 + 8 + 2 * tig];
#pragma unroll
        for (int nt = 0; nt < 2; nt++) {
            int n = wk * 16 + nt * 8 + g;
            uint32_t b0 = *(const uint32_t*)&ds[n * QPh + c0 + 2 * tig];
            uint32_t b1 = *(const uint32_t*)&ds[n * QPh + c0 + 8 + 2 * tig];
            mma_f16(acc[nt], a0, a1, a2, a3, b0, b1);
        }
    }

    float mx0 = -1000.f, mx1 = -1000.f;
#pragma unroll
    for (int nt = 0; nt < 2; nt++) {
        int n0 = wk * 16 + nt * 8 + 2 * tig;
        if (dmch[n0]) {
            mx0 = fmaxf(mx0, acc[nt][0]);
            mx1 = fmaxf(mx1, acc[nt][2]);
        }
        if (dmch[n0 + 1]) {
            mx0 = fmaxf(mx0, acc[nt][1]);
            mx1 = fmaxf(mx1, acc[nt][3]);
        }
    }
    mx0 = fmaxf(mx0, __shfl_xor_sync(0xffffffffu, mx0, 1));
    mx0 = fmaxf(mx0, __shfl_xor_sync(0xffffffffu, mx0, 2));
    mx1 = fmaxf(mx1, __shfl_xor_sync(0xffffffffu, mx1, 1));
    mx1 = fmaxf(mx1, __shfl_xor_sync(0xffffffffu, mx1, 2));
    __syncthreads();
    if (tig == 0) {
        redm[(wq * 16 + g) * 4 + wk]     = mx0;
        redm[(wq * 16 + g + 8) * 4 + wk] = mx1;
    }
    __syncthreads();

    if (t < 32) {
        float m = fmaxf(fmaxf(redm[t * 4 + 0], redm[t * 4 + 1]),
                        fmaxf(redm[t * 4 + 2], redm[t * 4 + 3]));
        g_pmax[(b * NSPL + ci) * LQ_ + t] = m;
    }

    // ---- last-CTA merge ----
    __threadfence();
    if (t == 0) {
        int old = atomicAdd(&g_cnt[b], 1);
        s_last = (old == NSPL - 1);
    }
    __syncthreads();
    if (!s_last) return;
    __threadfence();   // acquire: see other CTAs' g_pmax writes

    // CLS dot with all 256 threads (independent of gemm outputs)
    {
        const float* qp = qh   + (size_t)b * LQ_ * H_;
        const float* dp = dhid + (size_t)b * LD_ * H_;
        float p = 0.f;
        for (int h = t; h < H_; h += 256) p += qp[h] * dp[h];
        s_red[t] = p;
        __syncthreads();
        for (int s = 128; s > 0; s >>= 1) {
            if (t < s) s_red[t] += s_red[t + s];
            __syncthreads();
        }
    }

    if (t < 32) {
        float m = -1000.f;
#pragma unroll
        for (int ci2 = 0; ci2 < NSPL; ci2++)
            m = fmaxf(m, g_pmax[(b * NSPL + ci2) * LQ_ + t]);
        float term = qmask[b * LQ_ + t] ? m : 0.f;
#pragma unroll
        for (int o = 16; o >= 1; o >>= 1)
            term += __shfl_xor_sync(0xffffffffu, term, o);
        if (t == 0) {
            float w_  = 1.f / (1.f + expf(-merger[0]));
            float cls = s_red[0] * w_;
            float ts  = term * (1.f - w_);
            out[b]          = cls + ts;
            out[B_ + b]     = cls;
            out[2 * B_ + b] = ts;
            g_cnt[b] = 0;   // reset for next graph replay
        }
    }
}

extern "C" void kernel_launch(void* const* d_in, const int* in_sizes, int n_in,
                              void* d_out, int out_size)
{
    const float* query_hidden = (const float*)d_in[0];
    const float* doc_hidden   = (const float*)d_in[1];
    const int*   query_mask   = (const int*)  d_in[2];
    const int*   doc_mask     = (const int*)  d_in[3];
    const float* W_comp       = (const float*)d_in[4];
    const float* b_comp       = (const float*)d_in[5];
    const float* w_stop       = (const float*)d_in[6];
    const float* b_stop       = (const float*)d_in[7];
    const float* score_merger = (const float*)d_in[8];
    float* out = (float*)d_out;

    cudaFuncSetAttribute(gemm_all,
                         cudaFuncAttributeMaxDynamicSharedMemorySize, GEMM_SMEM);
    cudaFuncSetAttribute(score_fused,
                         cudaFuncAttributeMaxDynamicSharedMemorySize, SP_SMEM);

    prep_w<<<96, 256>>>(W_comp);
    gemm_all<<<QBLK + DBLK, 256, GEMM_SMEM>>>(
        query_hidden, doc_hidden, b_comp, w_stop, b_stop,
        query_mask, doc_mask);
    score_fused<<<B_ * NSPL, 256, SP_SMEM>>>(
        query_hidden, doc_hidden, doc_mask, query_mask, score_merger, out);
}